// round 17
// baseline (speedup 1.0000x reference)
#include <cuda_runtime.h>
#include <cuda_fp16.h>
#include <math.h>
#include <stdint.h>

// Problem constants: B=8, S=1024, D=768, H=12, DH=64
#define NB 8
#define NS 1024
#define ND 768
#define NH 12
#define NDH 64
#define NROWS (NB * NS)          // 8192
#define DFF (4 * ND)             // 3072

// ---------------- scratch (device globals) ----------------------------------
__device__ __half g_ln1h[NROWS * ND];
__device__ __half g_qh[NROWS * ND];
__device__ __half g_kh[NROWS * ND];
__device__ __half g_vh[NROWS * ND];
__device__ __half g_ln2h[NROWS * ND];
__device__ __half g_hidh[(size_t)NROWS * DFF];     // 48 MB
__device__ __half g_w1th[DFF * ND];                // W1^T [3072][768]
__device__ __half g_w2th[ND * DFF];                // W2^T [768][3072]
__device__ __half g_wqkvh[3 * NH * 64 * 64];       // per-head W^T [mat][h][e][d]

// ---------------- helpers ----------------------------------------------------
__device__ __forceinline__ uint32_t smem_u32(const void* p) {
    uint32_t a;
    asm("{ .reg .u64 t; cvta.to.shared.u64 t, %1; cvt.u32.u64 %0, t; }" : "=r"(a) : "l"(p));
    return a;
}
__device__ __forceinline__ void cp_async16(uint32_t s, const void* g) {
    asm volatile("cp.async.cg.shared.global [%0], [%1], 16;" :: "r"(s), "l"(g));
}
__device__ __forceinline__ void mma_f16(
    float& c0, float& c1, float& c2, float& c3,
    uint32_t a0, uint32_t a1, uint32_t a2, uint32_t a3,
    uint32_t b0, uint32_t b1)
{
    asm volatile(
        "mma.sync.aligned.m16n8k16.row.col.f32.f16.f16.f32 "
        "{%0,%1,%2,%3}, {%4,%5,%6,%7}, {%8,%9}, {%0,%1,%2,%3};"
        : "+f"(c0), "+f"(c1), "+f"(c2), "+f"(c3)
        : "r"(a0), "r"(a1), "r"(a2), "r"(a3), "r"(b0), "r"(b1));
}
__device__ __forceinline__ void ldmatrix_x4(
    uint32_t& r0, uint32_t& r1, uint32_t& r2, uint32_t& r3, uint32_t addr)
{
    asm volatile("ldmatrix.sync.aligned.m8n8.x4.shared.b16 {%0,%1,%2,%3}, [%4];"
        : "=r"(r0), "=r"(r1), "=r"(r2), "=r"(r3) : "r"(addr));
}
__device__ __forceinline__ void ldmatrix_x4_t(
    uint32_t& r0, uint32_t& r1, uint32_t& r2, uint32_t& r3, uint32_t addr)
{
    asm volatile("ldmatrix.sync.aligned.m8n8.x4.trans.shared.b16 {%0,%1,%2,%3}, [%4];"
        : "=r"(r0), "=r"(r1), "=r"(r2), "=r"(r3) : "r"(addr));
}
__device__ __forceinline__ float gelu_exact(float x) {
    return 0.5f * x * (1.0f + erff(x * 0.70710678118654752f));
}
__device__ __forceinline__ uint32_t pack_h2(float a, float b) {
    __half2 h = __floats2half2_rn(a, b);
    return *(uint32_t*)&h;
}

// ---------------- LayerNorm: one warp per row, fp16 output -------------------
__global__ __launch_bounds__(256) void ln_half(
    const float* __restrict__ x, const float* __restrict__ gw,
    const float* __restrict__ bw, __half* __restrict__ out)
{
    int wid = threadIdx.x >> 5, lane = threadIdx.x & 31;
    int row = blockIdx.x * 8 + wid;
    const float4* xr = (const float4*)(x + (size_t)row * ND);

    float4 v[6];
    float s = 0.f;
#pragma unroll
    for (int i = 0; i < 6; i++) {
        v[i] = xr[lane + 32 * i];
        s += v[i].x + v[i].y + v[i].z + v[i].w;
    }
#pragma unroll
    for (int o = 16; o > 0; o >>= 1) s += __shfl_xor_sync(0xffffffffu, s, o);
    float mean = s * (1.0f / (float)ND);

    float sq = 0.f;
#pragma unroll
    for (int i = 0; i < 6; i++) {
        float a = v[i].x - mean, b = v[i].y - mean, c = v[i].z - mean, d = v[i].w - mean;
        sq += a * a + b * b + c * c + d * d;
    }
#pragma unroll
    for (int o = 16; o > 0; o >>= 1) sq += __shfl_xor_sync(0xffffffffu, sq, o);
    float rstd = rsqrtf(sq * (1.0f / (float)ND) + 1e-5f);

    const float4* g4 = (const float4*)gw;
    const float4* b4 = (const float4*)bw;
    __half2* orow = (__half2*)(out + (size_t)row * ND);
#pragma unroll
    for (int i = 0; i < 6; i++) {
        int f = lane + 32 * i;
        float4 g = g4[f], b = b4[f];
        float o0 = (v[i].x - mean) * rstd * g.x + b.x;
        float o1 = (v[i].y - mean) * rstd * g.y + b.y;
        float o2 = (v[i].z - mean) * rstd * g.z + b.z;
        float o3 = (v[i].w - mean) * rstd * g.w + b.w;
        orow[f * 2]     = __floats2half2_rn(o0, o1);
        orow[f * 2 + 1] = __floats2half2_rn(o2, o3);
    }
}

// ---------------- transpose fp32 -> fp16: in[R][C] -> out[C][R] --------------
__global__ __launch_bounds__(256) void transpose_f16(
    const float* __restrict__ in, __half* __restrict__ out, int R, int C)
{
    __shared__ float tile[32][33];
    int c0 = blockIdx.x * 32, r0 = blockIdx.y * 32;
    int tx = threadIdx.x & 31, ty = threadIdx.x >> 5;
#pragma unroll
    for (int i = 0; i < 32; i += 8)
        tile[ty + i][tx] = in[(size_t)(r0 + ty + i) * C + c0 + tx];
    __syncthreads();
#pragma unroll
    for (int i = 0; i < 32; i += 8)
        out[(size_t)(c0 + ty + i) * R + r0 + tx] = __float2half_rn(tile[tx][ty + i]);
}

// ---------------- per-head weight transpose: W[h][d][e] -> half [m][h][e][d] -
__global__ __launch_bounds__(256) void wqkv_prep(
    const float* __restrict__ Wq, const float* __restrict__ Wk,
    const float* __restrict__ Wv, __half* __restrict__ out)
{
    int h = blockIdx.x, m = blockIdx.y;
    const float* W = (m == 0) ? Wq : ((m == 1) ? Wk : Wv);
    W += (size_t)h * 4096;
    __half* o = out + ((size_t)m * NH + h) * 4096;
    for (int idx = threadIdx.x; idx < 4096; idx += 256) {
        int d = idx >> 6, e = idx & 63;
        o[e * 64 + d] = __float2half_rn(W[d * 64 + e]);
    }
}

// ---------------- QKV: fp16 mma, CTA = 128 rows x 1 head --------------------
#define QS 72
#define QSW 36
#define QKV_SMEM ((128 * QS + 3 * 64 * QS) * 2)   // 46080 B

__global__ __launch_bounds__(256) void qkv_mma(
    const __half* __restrict__ ln1, const __half* __restrict__ wt,
    const float* __restrict__ bq, const float* __restrict__ bk,
    const float* __restrict__ bv,
    __half* __restrict__ q, __half* __restrict__ k, __half* __restrict__ v)
{
    extern __shared__ __half sh[];
    uint32_t sb = smem_u32(sh);
    uint32_t aW = sb + 128 * QS * 2;

    int bh = blockIdx.x;
    int h = bh % NH, b = bh / NH;
    int s0 = blockIdx.y * 128;
    int t = threadIdx.x, w = t >> 5, lane = t & 31;
    int gid = lane >> 2, tig = lane & 3;
    int rowb = (t & 7) + 8 * (t >> 5);
    int c0 = (t >> 3) & 3;

    const __half* Abase = ln1 + ((size_t)(b * NS + s0)) * ND + h * 64;
#pragma unroll
    for (int i = 0; i < 4; i++) {
        int row = rowb + 64 * (i >> 1);
        int c = c0 + 4 * (i & 1);
        cp_async16(sb + row * (QS * 2) + c * 16, Abase + (size_t)row * ND + c * 8);
    }
    const __half* Wbase = wt + (size_t)h * 4096;
#pragma unroll
    for (int m = 0; m < 3; m++)
#pragma unroll
        for (int i = 0; i < 2; i++) {
            int c = c0 + 4 * i;
            cp_async16(aW + m * (64 * QS * 2) + rowb * (QS * 2) + c * 16,
                       Wbase + (size_t)m * (NH * 4096) + rowb * 64 + c * 8);
        }
    asm volatile("cp.async.commit_group;\n\tcp.async.wait_group 0;" ::: "memory");
    __syncthreads();

    const uint32_t* Au = (const uint32_t*)sh;
    const uint32_t* Wu = (const uint32_t*)(sh + 128 * QS);
    int wrow = w * 16;

    uint32_t af[4][4];
#pragma unroll
    for (int kc = 0; kc < 4; kc++) {
        af[kc][0] = Au[(wrow + gid) * QSW + kc * 8 + tig];
        af[kc][1] = Au[(wrow + gid + 8) * QSW + kc * 8 + tig];
        af[kc][2] = Au[(wrow + gid) * QSW + kc * 8 + 4 + tig];
        af[kc][3] = Au[(wrow + gid + 8) * QSW + kc * 8 + 4 + tig];
    }
    float acc[3][8][4];
#pragma unroll
    for (int m = 0; m < 3; m++)
#pragma unroll
        for (int nf = 0; nf < 8; nf++)
#pragma unroll
            for (int r = 0; r < 4; r++) acc[m][nf][r] = 0.f;

#pragma unroll
    for (int kc = 0; kc < 4; kc++)
#pragma unroll
        for (int m = 0; m < 3; m++)
#pragma unroll
            for (int nf = 0; nf < 8; nf++) {
                uint32_t b0 = Wu[m * (64 * QSW) + (nf * 8 + gid) * QSW + kc * 8 + tig];
                uint32_t b1 = Wu[m * (64 * QSW) + (nf * 8 + gid) * QSW + kc * 8 + 4 + tig];
                mma_f16(acc[m][nf][0], acc[m][nf][1], acc[m][nf][2], acc[m][nf][3],
                        af[kc][0], af[kc][1], af[kc][2], af[kc][3], b0, b1);
            }

    size_t grow0 = (size_t)bh * NS + s0 + wrow + gid;
    size_t grow1 = grow0 + 8;
    const float* biases[3] = { bq + h * 64, bk + h * 64, bv + h * 64 };
    __half* dsts[3] = { q, k, v };
#pragma unroll
    for (int m = 0; m < 3; m++) {
        __half2* D = (__half2*)dsts[m];
        const float* bi = biases[m];
#pragma unroll
        for (int nf = 0; nf < 8; nf++) {
            int col = nf * 8 + 2 * tig;
            float b0 = bi[col], b1 = bi[col + 1];
            float v00 = acc[m][nf][0] + b0, v01 = acc[m][nf][1] + b1;
            float v10 = acc[m][nf][2] + b0, v11 = acc[m][nf][3] + b1;
            if (m == 0) { v00 *= 0.125f; v01 *= 0.125f; v10 *= 0.125f; v11 *= 0.125f; }
            D[grow0 * 32 + nf * 4 + tig] = __floats2half2_rn(v00, v01);
            D[grow1 * 32 + nf * 4 + tig] = __floats2half2_rn(v10, v11);
        }
    }
}

// ---------------- Attention: fp16 mma flash, register-resident P ------------
#define AS 72
#define ATTN_SMEM ((4 * 64 * AS) * 2)   // 36864 B

__global__ __launch_bounds__(256) void attn_h(
    const __half* __restrict__ q, const __half* __restrict__ k,
    const __half* __restrict__ v, const float* __restrict__ x,
    float* __restrict__ out)
{
    extern __shared__ __half sh[];
    uint32_t sb = smem_u32(sh);

    int bh = blockIdx.x;
    int h = bh % NH, b = bh / NH;
    int t = threadIdx.x, w = t >> 5, lane = t & 31;
    int gid = lane >> 2, tig = lane & 3;
    int qbase = blockIdx.y * 128;
    int wrow = w * 16;

    uint32_t qf[4][4];
    {
        const uint32_t* Qu = (const uint32_t*)(q + ((size_t)bh * NS + qbase + wrow) * NDH);
#pragma unroll
        for (int kc = 0; kc < 4; kc++) {
            qf[kc][0] = Qu[gid * 32 + kc * 8 + tig];
            qf[kc][1] = Qu[(gid + 8) * 32 + kc * 8 + tig];
            qf[kc][2] = Qu[gid * 32 + kc * 8 + 4 + tig];
            qf[kc][3] = Qu[(gid + 8) * 32 + kc * 8 + 4 + tig];
        }
    }

    float oa[8][4];
#pragma unroll
    for (int nf = 0; nf < 8; nf++) { oa[nf][0] = oa[nf][1] = oa[nf][2] = oa[nf][3] = 0.f; }
    float m0 = -1e30f, m1 = -1e30f, l0 = 0.f, l1 = 0.f;

    const __half* Kg0 = k + (size_t)bh * NS * NDH;
    const __half* Vg0 = v + (size_t)bh * NS * NDH;
    int lrow = t >> 3, lc = t & 7;

    {
#pragma unroll
        for (int p = 0; p < 2; p++) {
            int row = lrow + p * 32;
            cp_async16(sb + row * (AS * 2) + lc * 16, Kg0 + (size_t)row * NDH + lc * 8);
            cp_async16(sb + (2 * 64 * AS) * 2 + row * (AS * 2) + lc * 16,
                       Vg0 + (size_t)row * NDH + lc * 8);
        }
        asm volatile("cp.async.commit_group;" ::: "memory");
    }

    for (int kt = 0; kt < 16; kt++) {
        int cur = kt & 1, nxt = cur ^ 1;
        __syncthreads();
        if (kt + 1 < 16) {
            const __half* Kg = Kg0 + (size_t)(kt + 1) * 64 * NDH;
            const __half* Vg = Vg0 + (size_t)(kt + 1) * 64 * NDH;
            uint32_t kb = sb + nxt * (64 * AS * 2);
            uint32_t vb = sb + (2 * 64 * AS) * 2 + nxt * (64 * AS * 2);
#pragma unroll
            for (int p = 0; p < 2; p++) {
                int row = lrow + p * 32;
                cp_async16(kb + row * (AS * 2) + lc * 16, Kg + (size_t)row * NDH + lc * 8);
                cp_async16(vb + row * (AS * 2) + lc * 16, Vg + (size_t)row * NDH + lc * 8);
            }
            asm volatile("cp.async.commit_group;\n\tcp.async.wait_group 1;" ::: "memory");
        } else {
            asm volatile("cp.async.wait_group 0;" ::: "memory");
        }
        __syncthreads();

        uint32_t kbase = sb + cur * (64 * AS * 2);
        uint32_t vbase = sb + (2 * 64 * AS) * 2 + cur * (64 * AS * 2);

        float sa[8][4];
#pragma unroll
        for (int nf = 0; nf < 8; nf++) { sa[nf][0] = sa[nf][1] = sa[nf][2] = sa[nf][3] = 0.f; }
#pragma unroll
        for (int kc = 0; kc < 4; kc++)
#pragma unroll
            for (int nf2 = 0; nf2 < 4; nf2++) {
                int nrow = (2 * nf2 + ((lane >> 4) & 1)) * 8 + (lane & 7);
                uint32_t addr = kbase + nrow * (AS * 2) + kc * 32 + ((lane >> 3) & 1) * 16;
                uint32_t b0, b1, b2, b3;
                ldmatrix_x4(b0, b1, b2, b3, addr);
                mma_f16(sa[2 * nf2][0], sa[2 * nf2][1], sa[2 * nf2][2], sa[2 * nf2][3],
                        qf[kc][0], qf[kc][1], qf[kc][2], qf[kc][3], b0, b1);
                mma_f16(sa[2 * nf2 + 1][0], sa[2 * nf2 + 1][1], sa[2 * nf2 + 1][2], sa[2 * nf2 + 1][3],
                        qf[kc][0], qf[kc][1], qf[kc][2], qf[kc][3], b2, b3);
            }

        float tm0 = -1e30f, tm1 = -1e30f;
#pragma unroll
        for (int nf = 0; nf < 8; nf++) {
            tm0 = fmaxf(tm0, fmaxf(sa[nf][0], sa[nf][1]));
            tm1 = fmaxf(tm1, fmaxf(sa[nf][2], sa[nf][3]));
        }
        tm0 = fmaxf(tm0, __shfl_xor_sync(0xffffffffu, tm0, 1));
        tm0 = fmaxf(tm0, __shfl_xor_sync(0xffffffffu, tm0, 2));
        tm1 = fmaxf(tm1, __shfl_xor_sync(0xffffffffu, tm1, 1));
        tm1 = fmaxf(tm1, __shfl_xor_sync(0xffffffffu, tm1, 2));
        float mn0 = fmaxf(m0, tm0), mn1 = fmaxf(m1, tm1);
        float cc0 = __expf(m0 - mn0), cc1 = __expf(m1 - mn1);
        m0 = mn0; m1 = mn1;

        uint32_t pf[4][4];
        float ls0 = 0.f, ls1 = 0.f;
#pragma unroll
        for (int kc = 0; kc < 4; kc++) {
            int nf = 2 * kc;
            float p00 = __expf(sa[nf][0] - mn0);
            float p01 = __expf(sa[nf][1] - mn0);
            float p10 = __expf(sa[nf][2] - mn1);
            float p11 = __expf(sa[nf][3] - mn1);
            float q00 = __expf(sa[nf + 1][0] - mn0);
            float q01 = __expf(sa[nf + 1][1] - mn0);
            float q10 = __expf(sa[nf + 1][2] - mn1);
            float q11 = __expf(sa[nf + 1][3] - mn1);
            ls0 += p00 + p01 + q00 + q01;
            ls1 += p10 + p11 + q10 + q11;
            pf[kc][0] = pack_h2(p00, p01);
            pf[kc][1] = pack_h2(p10, p11);
            pf[kc][2] = pack_h2(q00, q01);
            pf[kc][3] = pack_h2(q10, q11);
        }
        ls0 += __shfl_xor_sync(0xffffffffu, ls0, 1);
        ls0 += __shfl_xor_sync(0xffffffffu, ls0, 2);
        ls1 += __shfl_xor_sync(0xffffffffu, ls1, 1);
        ls1 += __shfl_xor_sync(0xffffffffu, ls1, 2);
        l0 = l0 * cc0 + ls0;
        l1 = l1 * cc1 + ls1;
#pragma unroll
        for (int nf = 0; nf < 8; nf++) {
            oa[nf][0] *= cc0; oa[nf][1] *= cc0;
            oa[nf][2] *= cc1; oa[nf][3] *= cc1;
        }

        int g = lane >> 3, r = lane & 7;
#pragma unroll
        for (int kc = 0; kc < 4; kc++) {
#pragma unroll
            for (int nf2 = 0; nf2 < 4; nf2++) {
                uint32_t addr = vbase + (kc * 16 + (g & 1) * 8 + r) * (AS * 2)
                                      + nf2 * 32 + (g >> 1) * 16;
                uint32_t r0, r1, r2, r3;
                ldmatrix_x4_t(r0, r1, r2, r3, addr);
                mma_f16(oa[2 * nf2][0], oa[2 * nf2][1], oa[2 * nf2][2], oa[2 * nf2][3],
                        pf[kc][0], pf[kc][1], pf[kc][2], pf[kc][3], r0, r1);
                mma_f16(oa[2 * nf2 + 1][0], oa[2 * nf2 + 1][1], oa[2 * nf2 + 1][2], oa[2 * nf2 + 1][3],
                        pf[kc][0], pf[kc][1], pf[kc][2], pf[kc][3], r2, r3);
            }
        }
    }

    float inv0 = 1.f / l0, inv1 = 1.f / l1;
    int r0g = qbase + wrow + gid;
    size_t o0 = ((size_t)(b * NS) + r0g) * ND + h * NDH;
    size_t o1 = o0 + (size_t)8 * ND;
#pragma unroll
    for (int nf = 0; nf < 8; nf++) {
        int col = nf * 8 + 2 * tig;
        float2 x0 = *(const float2*)(x + o0 + col);
        float2 x1 = *(const float2*)(x + o1 + col);
        *(float2*)(out + o0 + col) = make_float2(x0.x + oa[nf][0] * inv0, x0.y + oa[nf][1] * inv0);
        *(float2*)(out + o1 + col) = make_float2(x1.x + oa[nf][2] * inv1, x1.y + oa[nf][3] * inv1);
    }
}

// ---------------- FFN GEMM1: 128x256 CTA tile, 64x64 warp tile --------------
// smem per stage: A 128x72 + B 256x72 halves; 2 stages = 110592 B, 1 CTA/SM.
#define FS2 72
#define ABUF3 (128 * FS2)
#define BBUF3 (256 * FS2)
#define STAGE3 (ABUF3 + BBUF3)
#define GEMM1_SMEM (2 * STAGE3 * 2)      // 110592 B

__global__ __launch_bounds__(256) void gemm_big(
    const __half* __restrict__ A, const __half* __restrict__ Bt,
    __half* __restrict__ C, int K, int N)
{
    extern __shared__ __half sh[];
    uint32_t sb = smem_u32(sh);

    int t = threadIdx.x, w = t >> 5, lane = t & 31;
    int gid = lane >> 2, tig = lane & 3;
    int wm = w >> 2, wn = w & 3;          // 2 x 4 warp grid, warp tile 64x64
    int m0 = blockIdx.y * 128, n0 = blockIdx.x * 256;
    int lrow = t >> 3, lc = t & 7;

    const __half* Ag = A + (size_t)m0 * K;
    const __half* Bg = Bt + (size_t)n0 * K;

    float acc[4][8][4];
#pragma unroll
    for (int i = 0; i < 4; i++)
#pragma unroll
        for (int j = 0; j < 8; j++)
#pragma unroll
            for (int r = 0; r < 4; r++) acc[i][j][r] = 0.f;

    int nkt = K >> 6;
    // prefetch kt=0 -> stage 0
    {
        uint32_t dA = sb, dB = sb + ABUF3 * 2;
#pragma unroll
        for (int p = 0; p < 4; p++) {
            int row = lrow + p * 32;
            cp_async16(dA + row * (FS2 * 2) + lc * 16, Ag + (size_t)row * K + lc * 8);
        }
#pragma unroll
        for (int p = 0; p < 8; p++) {
            int row = lrow + p * 32;
            cp_async16(dB + row * (FS2 * 2) + lc * 16, Bg + (size_t)row * K + lc * 8);
        }
        asm volatile("cp.async.commit_group;" ::: "memory");
    }

    for (int kt = 0; kt < nkt; kt++) {
        int cur = kt & 1, nxt = cur ^ 1;
        __syncthreads();
        if (kt + 1 < nkt) {
            uint32_t dA = sb + nxt * (STAGE3 * 2), dB = dA + ABUF3 * 2;
            int kh = (kt + 1) * 64;
#pragma unroll
            for (int p = 0; p < 4; p++) {
                int row = lrow + p * 32;
                cp_async16(dA + row * (FS2 * 2) + lc * 16, Ag + (size_t)row * K + kh + lc * 8);
            }
#pragma unroll
            for (int p = 0; p < 8; p++) {
                int row = lrow + p * 32;
                cp_async16(dB + row * (FS2 * 2) + lc * 16, Bg + (size_t)row * K + kh + lc * 8);
            }
            asm volatile("cp.async.commit_group;\n\tcp.async.wait_group 1;" ::: "memory");
        } else {
            asm volatile("cp.async.wait_group 0;" ::: "memory");
        }
        __syncthreads();

        uint32_t Ab = sb + cur * (STAGE3 * 2);
        uint32_t Bb = Ab + ABUF3 * 2;

#pragma unroll
        for (int ks = 0; ks < 4; ks++) {
            uint32_t a[4][4];
#pragma unroll
            for (int mf = 0; mf < 4; mf++) {
                int arow = wm * 64 + mf * 16 + (lane & 15);
                uint32_t addr = Ab + arow * (FS2 * 2) + ks * 32 + ((lane >> 4) & 1) * 16;
                ldmatrix_x4(a[mf][0], a[mf][1], a[mf][2], a[mf][3], addr);
            }
            uint32_t bb[8][2];
#pragma unroll
            for (int nf2 = 0; nf2 < 4; nf2++) {
                int brow = wn * 64 + (2 * nf2 + ((lane >> 4) & 1)) * 8 + (lane & 7);
                uint32_t addr = Bb + brow * (FS2 * 2) + ks * 32 + ((lane >> 3) & 1) * 16;
                ldmatrix_x4(bb[2 * nf2][0], bb[2 * nf2][1],
                            bb[2 * nf2 + 1][0], bb[2 * nf2 + 1][1], addr);
            }
#pragma unroll
            for (int mf = 0; mf < 4; mf++)
#pragma unroll
                for (int nf = 0; nf < 8; nf++)
                    mma_f16(acc[mf][nf][0], acc[mf][nf][1], acc[mf][nf][2], acc[mf][nf][3],
                            a[mf][0], a[mf][1], a[mf][2], a[mf][3],
                            bb[nf][0], bb[nf][1]);
        }
    }

    __half2* C2 = (__half2*)C;
#pragma unroll
    for (int mf = 0; mf < 4; mf++) {
#pragma unroll
        for (int nf = 0; nf < 8; nf++) {
            int row = m0 + wm * 64 + mf * 16 + gid;
            int col = n0 + wn * 64 + nf * 8 + tig * 2;
            C2[(size_t)row * (N / 2) + col / 2] =
                __floats2half2_rn(gelu_exact(acc[mf][nf][0]), gelu_exact(acc[mf][nf][1]));
            C2[(size_t)(row + 8) * (N / 2) + col / 2] =
                __floats2half2_rn(gelu_exact(acc[mf][nf][2]), gelu_exact(acc[mf][nf][3]));
        }
    }
}

// ---------------- FFN GEMM2: 128x128 tile, Ktile 64, double buffer ----------
#define FBUF2 (128 * FS2)
#define GEMM_SMEM (4 * FBUF2 * 2)         // 73728 B

__global__ __launch_bounds__(256) void gemm_res(
    const __half* __restrict__ A, const __half* __restrict__ Bt,
    float* __restrict__ C, int K, int N)
{
    extern __shared__ __half sh[];
    uint32_t sb = smem_u32(sh);

    int t = threadIdx.x, w = t >> 5, lane = t & 31;
    int gid = lane >> 2, tig = lane & 3;
    int wm = w >> 2, wn = w & 3;
    int m0 = blockIdx.y * 128, n0 = blockIdx.x * 128;
    int lrow = t >> 3, lc = t & 7;

    const __half* Ag = A + (size_t)m0 * K;
    const __half* Bg = Bt + (size_t)n0 * K;

    float acc[4][4][4];
#pragma unroll
    for (int i = 0; i < 4; i++)
#pragma unroll
        for (int j = 0; j < 4; j++)
#pragma unroll
            for (int r = 0; r < 4; r++) acc[i][j][r] = 0.f;

    int nkt = K >> 6;
    {
        uint32_t dA = sb, dB = sb + FBUF2 * 2;
#pragma unroll
        for (int p = 0; p < 4; p++) {
            int row = lrow + p * 32;
            cp_async16(dA + row * (FS2 * 2) + lc * 16, Ag + (size_t)row * K + lc * 8);
            cp_async16(dB + row * (FS2 * 2) + lc * 16, Bg + (size_t)row * K + lc * 8);
        }
        asm volatile("cp.async.commit_group;" ::: "memory");
    }

    for (int kt = 0; kt < nkt; kt++) {
        int cur = kt & 1, nxt = cur ^ 1;
        __syncthreads();
        if (kt + 1 < nkt) {
            uint32_t dA = sb + nxt * (2 * FBUF2 * 2), dB = dA + FBUF2 * 2;
            int kh = (kt + 1) * 64;
#pragma unroll
            for (int p = 0; p < 4; p++) {
                int row = lrow + p * 32;
                cp_async16(dA + row * (FS2 * 2) + lc * 16, Ag + (size_t)row * K + kh + lc * 8);
                cp_async16(dB + row * (FS2 * 2) + lc * 16, Bg + (size_t)row * K + kh + lc * 8);
            }
            asm volatile("cp.async.commit_group;\n\tcp.async.wait_group 1;" ::: "memory");
        } else {
            asm volatile("cp.async.wait_group 0;" ::: "memory");
        }
        __syncthreads();

        uint32_t Ab = sb + cur * (2 * FBUF2 * 2);
        uint32_t Bb = Ab + FBUF2 * 2;

#pragma unroll
        for (int ks = 0; ks < 4; ks++) {
            uint32_t a[4][4];
#pragma unroll
            for (int mf = 0; mf < 4; mf++) {
                int arow = wm * 64 + mf * 16 + (lane & 15);
                uint32_t addr = Ab + arow * (FS2 * 2) + ks * 32 + ((lane >> 4) & 1) * 16;
                ldmatrix_x4(a[mf][0], a[mf][1], a[mf][2], a[mf][3], addr);
            }
            uint32_t bb[4][2];
#pragma unroll
            for (int nf2 = 0; nf2 < 2; nf2++) {
                int brow = wn * 32 + (2 * nf2 + ((lane >> 4) & 1)) * 8 + (lane & 7);
                uint32_t addr = Bb + brow * (FS2 * 2) + ks * 32 + ((lane >> 3) & 1) * 16;
                ldmatrix_x4(bb[2 * nf2][0], bb[2 * nf2][1],
                            bb[2 * nf2 + 1][0], bb[2 * nf2 + 1][1], addr);
            }
#pragma unroll
            for (int mf = 0; mf < 4; mf++)
#pragma unroll
                for (int nf = 0; nf < 4; nf++)
                    mma_f16(acc[mf][nf][0], acc[mf][nf][1], acc[mf][nf][2], acc[mf][nf][3],
                            a[mf][0], a[mf][1], a[mf][2], a[mf][3],
                            bb[nf][0], bb[nf][1]);
        }
    }

#pragma unroll
    for (int mf = 0; mf < 4; mf++) {
#pragma unroll
        for (int nf = 0; nf < 4; nf++) {
            int row = m0 + wm * 64 + mf * 16 + gid;
            int col = n0 + wn * 32 + nf * 8 + tig * 2;
            float* p0 = C + (size_t)row * N + col;
            float* p1 = C + (size_t)(row + 8) * N + col;
            float2 c0v = *(float2*)p0, c1v = *(float2*)p1;
            *(float2*)p0 = make_float2(c0v.x + acc[mf][nf][0], c0v.y + acc[mf][nf][1]);
            *(float2*)p1 = make_float2(c1v.x + acc[mf][nf][2], c1v.y + acc[mf][nf][3]);
        }
    }
}

// ---------------- host launcher ---------------------------------------------
extern "C" void kernel_launch(void* const* d_in, const int* in_sizes, int n_in,
                              void* d_out, int out_size)
{
    const float* x     = (const float*)d_in[0];
    const float* ln1_g = (const float*)d_in[1];
    const float* ln1_b = (const float*)d_in[2];
    const float* Wq    = (const float*)d_in[3];
    const float* bq    = (const float*)d_in[4];
    const float* Wk    = (const float*)d_in[5];
    const float* bk    = (const float*)d_in[6];
    const float* Wv    = (const float*)d_in[7];
    const float* bv    = (const float*)d_in[8];
    const float* ln2_g = (const float*)d_in[9];
    const float* ln2_b = (const float*)d_in[10];
    const float* W1    = (const float*)d_in[11];
    const float* W2    = (const float*)d_in[12];
    float* out = (float*)d_out;

    __half *ln1p, *qp, *kp, *vp, *ln2p, *hidp, *w1tp, *w2tp, *wqkvp;
    cudaGetSymbolAddress((void**)&ln1p,  g_ln1h);
    cudaGetSymbolAddress((void**)&qp,    g_qh);
    cudaGetSymbolAddress((void**)&kp,    g_kh);
    cudaGetSymbolAddress((void**)&vp,    g_vh);
    cudaGetSymbolAddress((void**)&ln2p,  g_ln2h);
    cudaGetSymbolAddress((void**)&hidp,  g_hidh);
    cudaGetSymbolAddress((void**)&w1tp,  g_w1th);
    cudaGetSymbolAddress((void**)&w2tp,  g_w2th);
    cudaGetSymbolAddress((void**)&wqkvp, g_wqkvh);

    cudaFuncSetAttribute(qkv_mma,  cudaFuncAttributeMaxDynamicSharedMemorySize, QKV_SMEM);
    cudaFuncSetAttribute(attn_h,   cudaFuncAttributeMaxDynamicSharedMemorySize, ATTN_SMEM);
    cudaFuncSetAttribute(gemm_big, cudaFuncAttributeMaxDynamicSharedMemorySize, GEMM1_SMEM);
    cudaFuncSetAttribute(gemm_res, cudaFuncAttributeMaxDynamicSharedMemorySize, GEMM_SMEM);

    // weight preps
    transpose_f16<<<dim3(DFF / 32, ND / 32), 256>>>(W1, w1tp, ND, DFF);   // [3072][768]
    transpose_f16<<<dim3(ND / 32, DFF / 32), 256>>>(W2, w2tp, DFF, ND);   // [768][3072]
    wqkv_prep<<<dim3(NH, 3), 256>>>(Wq, Wk, Wv, wqkvp);
    // LN1 -> fp16 (warp per row)
    ln_half<<<NROWS / 8, 256>>>(x, ln1_g, ln1_b, ln1p);
    // QKV (fp16 mma, Q pre-scaled by 1/8)
    qkv_mma<<<dim3(NB * NH, NS / 128), 256, QKV_SMEM>>>(ln1p, wqkvp, bq, bk, bv, qp, kp, vp);
    // attention + residual (out = x + msa)
    attn_h<<<dim3(NB * NH, NS / 128), 256, ATTN_SMEM>>>(qp, kp, vp, x, out);
    // LN2 -> fp16
    ln_half<<<NROWS / 8, 256>>>(out, ln2_g, ln2_b, ln2p);
    // FFN up + GELU -> fp16 hid (128x256 tiles)
    gemm_big<<<dim3(DFF / 256, NROWS / 128), 256, GEMM1_SMEM>>>(ln2p, w1tp, hidp, ND, DFF);
    // FFN down + residual into out (128x128 tiles)
    gemm_res<<<dim3(ND / 128, NROWS / 128), 256, GEMM_SMEM>>>(hidp, w2tp, out, DFF, ND);
}